// round 1
// baseline (speedup 1.0000x reference)
#include <cuda_runtime.h>
#include <math.h>

#define NS 3000

// Scratch (static device arrays — no allocation). Max intermediate: [3000, 256].
__device__ float g_buf1[NS * 256];
__device__ float g_buf2[NS * 256];

enum { EPI_NONE = 0, EPI_TANH = 1, EPI_SIG = 2 };

// C[M,N] = epi( A[M,K] @ B )
//   BT=false: B is [K,N] row-major
//   BT=true : B is [N,K] row-major (computes A @ B^T)
// Requires: K % 8 == 0, N % 4 == 0 (true for all call sites: K in {3000,256,128,64},
// N in {3000,256,128,64}).
template <int EPI, bool BT>
__global__ void __launch_bounds__(256)
sgemm_kernel(const float* __restrict__ A, const float* __restrict__ B,
             float* __restrict__ C, int M, int N, int K)
{
    __shared__ float As[8][128];
    __shared__ float Bs[8][128];

    const int tid  = threadIdx.x;
    const int brow = blockIdx.y * 128;
    const int bcol = blockIdx.x * 128;
    const int tx = tid & 15;   // 16 cols of threads
    const int ty = tid >> 4;   // 16 rows of threads

    float acc[8][8];
#pragma unroll
    for (int i = 0; i < 8; i++)
#pragma unroll
        for (int j = 0; j < 8; j++) acc[i][j] = 0.f;

    // A tile load mapping: 128 rows x 8 k, 2 float4 per row -> 256 threads
    const int aRow = tid >> 1;
    const int aSeg = (tid & 1) * 4;
    const int ga   = brow + aRow;

    const int nk = K >> 3;
    for (int kt = 0; kt < nk; ++kt) {
        const int k0 = kt * 8;

        float4 va = make_float4(0.f, 0.f, 0.f, 0.f);
        if (ga < M) va = *(const float4*)(A + (size_t)ga * K + k0 + aSeg);
        As[aSeg + 0][aRow] = va.x;
        As[aSeg + 1][aRow] = va.y;
        As[aSeg + 2][aRow] = va.z;
        As[aSeg + 3][aRow] = va.w;

        if (BT) {
            // B[N,K] row-major: Bs[k][j] = B[j*K + k]
            const int bRow = tid >> 1;
            const int bSeg = (tid & 1) * 4;
            const int gb   = bcol + bRow;
            float4 vb = make_float4(0.f, 0.f, 0.f, 0.f);
            if (gb < N) vb = *(const float4*)(B + (size_t)gb * K + k0 + bSeg);
            Bs[bSeg + 0][bRow] = vb.x;
            Bs[bSeg + 1][bRow] = vb.y;
            Bs[bSeg + 2][bRow] = vb.z;
            Bs[bSeg + 3][bRow] = vb.w;
        } else {
            // B[K,N] row-major: Bs[k][j] = B[k*N + j]
            const int bRow = tid >> 5;          // k within tile (0..7)
            const int bCol = (tid & 31) * 4;    // col within tile
            const int gb   = bcol + bCol;
            float4 vb = make_float4(0.f, 0.f, 0.f, 0.f);
            if (gb < N) vb = *(const float4*)(B + (size_t)(k0 + bRow) * N + gb);
            *(float4*)&Bs[bRow][bCol] = vb;
        }
        __syncthreads();

#pragma unroll
        for (int k = 0; k < 8; k++) {
            float a[8], b[8];
#pragma unroll
            for (int i = 0; i < 8; i++) a[i] = As[k][ty * 8 + i];
#pragma unroll
            for (int j = 0; j < 8; j++) b[j] = Bs[k][tx * 8 + j];
#pragma unroll
            for (int i = 0; i < 8; i++)
#pragma unroll
                for (int j = 0; j < 8; j++) acc[i][j] += a[i] * b[j];
        }
        __syncthreads();
    }

    // Epilogue: fused activation + vectorized guarded store
#pragma unroll
    for (int i = 0; i < 8; i++) {
        const int r = brow + ty * 8 + i;
        if (r >= M) continue;
#pragma unroll
        for (int j0 = 0; j0 < 8; j0 += 4) {
            const int c = bcol + tx * 8 + j0;
            if (c >= N) continue;   // N % 4 == 0 so c<N implies c+3<N
            float4 v;
            float* pv = &v.x;
#pragma unroll
            for (int j = 0; j < 4; j++) {
                float x = acc[i][j0 + j];
                if (EPI == EPI_TANH) x = tanhf(x);
                else if (EPI == EPI_SIG) x = 1.f / (1.f + __expf(-x));
                pv[j] = x;
            }
            *(float4*)(C + (size_t)r * N + c) = v;
        }
    }
}

static void launch_gemm(const float* A, const float* B, float* C,
                        int M, int N, int K, int epi, bool bt)
{
    dim3 grid((N + 127) / 128, (M + 127) / 128);
    if (bt) {
        if (epi == EPI_SIG)
            sgemm_kernel<EPI_SIG, true><<<grid, 256>>>(A, B, C, M, N, K);
        else
            sgemm_kernel<EPI_NONE, true><<<grid, 256>>>(A, B, C, M, N, K);
    } else {
        if (epi == EPI_TANH)
            sgemm_kernel<EPI_TANH, false><<<grid, 256>>>(A, B, C, M, N, K);
        else
            sgemm_kernel<EPI_NONE, false><<<grid, 256>>>(A, B, C, M, N, K);
    }
}

extern "C" void kernel_launch(void* const* d_in, const int* in_sizes, int n_in,
                              void* d_out, int out_size)
{
    const float* omics1 = (const float*)d_in[0];
    const float* omics2 = (const float*)d_in[1];
    const float* adjF1  = (const float*)d_in[2];
    const float* adjF2  = (const float*)d_in[3];
    const float* adjS1  = (const float*)d_in[4];
    const float* adjS2  = (const float*)d_in[5];

    const float* W[4][3];
    for (int e = 0; e < 4; e++)
        for (int l = 0; l < 3; l++)
            W[e][l] = (const float*)d_in[6 + e * 3 + l];

    float* out = (float*)d_out;

    float *b1 = nullptr, *b2 = nullptr;
    cudaGetSymbolAddress((void**)&b1, g_buf1);
    cudaGetSymbolAddress((void**)&b2, g_buf2);

    const float* xs[4]   = {omics1, omics2, omics1, omics2};
    const float* adjs[4] = {adjF1, adjF2, adjS1, adjS2};

    for (int e = 0; e < 4; e++) {
        // z1 = adj @ tanh(x @ W1)
        launch_gemm(xs[e],   W[e][0], b1, NS, 256, NS,  EPI_TANH, false);
        launch_gemm(adjs[e], b1,      b2, NS, 256, NS,  EPI_NONE, false);
        // z2 = adj @ tanh(z1 @ W2)
        launch_gemm(b2,      W[e][1], b1, NS, 128, 256, EPI_TANH, false);
        launch_gemm(adjs[e], b1,      b2, NS, 128, NS,  EPI_NONE, false);
        // z3 = adj @ (z2 @ W3)
        launch_gemm(b2,      W[e][2], b1, NS, 64,  128, EPI_NONE, false);
        launch_gemm(adjs[e], b1,      b2, NS, 64,  NS,  EPI_NONE, false);
        // adj_hat = sigmoid(z3 @ z3^T)
        launch_gemm(b2, b2, out + (size_t)e * NS * NS, NS, NS, 64, EPI_SIG, true);
    }
}

// round 2
// speedup vs baseline: 6.3388x; 6.3388x over previous
#include <cuda_runtime.h>
#include <mma.h>
#include <math.h>

using namespace nvcuda;

#define NS   3000
#define ENC1 256

// Scratch: two ping-pong buffers per encoder, max intermediate [3000, 256].
__device__ float g_bufA[4][NS * ENC1];
__device__ float g_bufB[4][NS * ENC1];

enum { EPI_NONE = 0, EPI_TANH = 1, EPI_SIG = 2 };

struct GArgs {
    const float* A[4];
    const float* B[4];
    float*       C[4];
    int M, N, K;
};

__device__ __forceinline__ void cp_async16(float* s, const float* g, bool pred) {
    if (pred) {
        unsigned saddr = (unsigned)__cvta_generic_to_shared(s);
        asm volatile("cp.async.cg.shared.global [%0], [%1], 16;\n"
                     :: "r"(saddr), "l"(g));
    } else {
        *(float4*)s = make_float4(0.f, 0.f, 0.f, 0.f);
    }
}
__device__ __forceinline__ void cp_commit() {
    asm volatile("cp.async.commit_group;\n");
}
template <int NMAX>
__device__ __forceinline__ void cp_wait() {
    asm volatile("cp.async.wait_group %0;\n" :: "n"(NMAX));
}

// Grouped GEMM: C[g] = epi(A[g] @ B[g])   (BT=true: A[g] @ B[g]^T, B[g] is [N,K])
// Block tile 128x128x32, 8 warps (2x4), warp tile 64x32, wmma m16n16k8 tf32.
// Requires K%4==0 and N%4==0 (all call sites satisfy this). M,N edges guarded.
template <int EPI, bool BT>
__global__ void __launch_bounds__(256)
mm_kernel(GArgs ga)
{
    constexpr int BM = 128, BN = 128, BK = 32;
    constexpr int LDA   = BK + 8;   // 40  As[row][k]
    constexpr int LDB_N = BN + 8;   // 136 Bs[k][n]   (BT=false)
    constexpr int LDB_T = BK + 8;   // 40  BsT[n][k]  (BT=true)
    constexpr int ASZ = BM * LDA;                       // per-stage A floats
    constexpr int BSZ = BT ? BN * LDB_T : BK * LDB_N;   // per-stage B floats

    extern __shared__ float smem[];
    float* As = smem;             // [2][ASZ]
    float* Bs = smem + 2 * ASZ;   // [2][BSZ]

    const int g = blockIdx.z;
    const float* __restrict__ A = ga.A[g];
    const float* __restrict__ B = ga.B[g];
    float* __restrict__ C = ga.C[g];
    const int M = ga.M, N = ga.N, K = ga.K;

    const int tid = threadIdx.x;
    const int wid = tid >> 5;
    const int lane = tid & 31;
    const int wm = wid >> 2;   // 0..1 (M dir)
    const int wn = wid & 3;    // 0..3 (N dir)
    const int brow = blockIdx.y * BM;
    const int bcol = blockIdx.x * BN;

    wmma::fragment<wmma::accumulator, 16, 16, 8, float> acc[4][2];
#pragma unroll
    for (int i = 0; i < 4; i++)
#pragma unroll
        for (int j = 0; j < 2; j++) wmma::fill_fragment(acc[i][j], 0.f);

    const int nkt = (K + BK - 1) / BK;

    // ---- tile loaders (256 threads, 4 float4 each per operand) ----
    auto load_tile = [&](int kt, int p) {
        const int k0 = kt * BK;
        // A: 128 rows x 32 k  (8 float4 per row)
#pragma unroll
        for (int i = 0; i < 4; i++) {
            int lin = tid + i * 256;
            int row = lin >> 3, c4 = (lin & 7) * 4;
            int gr = brow + row, gk = k0 + c4;
            cp_async16(As + p * ASZ + row * LDA + c4,
                       A + (size_t)gr * K + gk,
                       (gr < M) && (gk < K));
        }
        if (!BT) {
            // B[K,N]: 32 k-rows x 128 n  (32 float4 per row)
#pragma unroll
            for (int i = 0; i < 4; i++) {
                int lin = tid + i * 256;
                int kr = lin >> 5, c4 = (lin & 31) * 4;
                int gk = k0 + kr, gn = bcol + c4;
                cp_async16(Bs + p * BSZ + kr * LDB_N + c4,
                           B + (size_t)gk * N + gn,
                           (gk < K) && (gn < N));
            }
        } else {
            // B[N,K]: 128 n-rows x 32 k
#pragma unroll
            for (int i = 0; i < 4; i++) {
                int lin = tid + i * 256;
                int nr = lin >> 3, c4 = (lin & 7) * 4;
                int gn = bcol + nr, gk = k0 + c4;
                cp_async16(Bs + p * BSZ + nr * LDB_T + c4,
                           B + (size_t)gn * K + gk,
                           (gn < N) && (gk < K));
            }
        }
        cp_commit();
    };

    load_tile(0, 0);

    for (int kt = 0; kt < nkt; ++kt) {
        const int p = kt & 1;
        if (kt + 1 < nkt) {
            load_tile(kt + 1, p ^ 1);
            cp_wait<1>();
        } else {
            cp_wait<0>();
        }
        __syncthreads();

        float* as = As + p * ASZ + (wm * 64) * LDA;
#pragma unroll
        for (int ks = 0; ks < 4; ks++) {
            wmma::fragment<wmma::matrix_a, 16, 16, 8, wmma::precision::tf32,
                           wmma::row_major> af[4];
#pragma unroll
            for (int i = 0; i < 4; i++) {
                wmma::load_matrix_sync(af[i], as + (i * 16) * LDA + ks * 8, LDA);
#pragma unroll
                for (int t = 0; t < af[i].num_elements; t++)
                    af[i].x[t] = wmma::__float_to_tf32(af[i].x[t]);
            }
            if (!BT) {
                wmma::fragment<wmma::matrix_b, 16, 16, 8, wmma::precision::tf32,
                               wmma::row_major> bf[2];
                float* bs = Bs + p * BSZ + (ks * 8) * LDB_N + wn * 32;
#pragma unroll
                for (int j = 0; j < 2; j++) {
                    wmma::load_matrix_sync(bf[j], bs + j * 16, LDB_N);
#pragma unroll
                    for (int t = 0; t < bf[j].num_elements; t++)
                        bf[j].x[t] = wmma::__float_to_tf32(bf[j].x[t]);
                }
#pragma unroll
                for (int i = 0; i < 4; i++)
#pragma unroll
                    for (int j = 0; j < 2; j++)
                        wmma::mma_sync(acc[i][j], af[i], bf[j], acc[i][j]);
            } else {
                wmma::fragment<wmma::matrix_b, 16, 16, 8, wmma::precision::tf32,
                               wmma::col_major> bf[2];
                float* bs = Bs + p * BSZ + (wn * 32) * LDB_T + ks * 8;
#pragma unroll
                for (int j = 0; j < 2; j++) {
                    wmma::load_matrix_sync(bf[j], bs + (j * 16) * LDB_T, LDB_T);
#pragma unroll
                    for (int t = 0; t < bf[j].num_elements; t++)
                        bf[j].x[t] = wmma::__float_to_tf32(bf[j].x[t]);
                }
#pragma unroll
                for (int i = 0; i < 4; i++)
#pragma unroll
                    for (int j = 0; j < 2; j++)
                        wmma::mma_sync(acc[i][j], af[i], bf[j], acc[i][j]);
            }
        }
        __syncthreads();
    }

    // ---- epilogue: activation + store (fast path interior, staged for edges) ----
    __syncthreads();                       // safe to reuse smem for edge patches
    float* patch = smem + wid * (16 * 20); // per-warp 16x16 staging, ld=20

#pragma unroll
    for (int i = 0; i < 4; i++) {
#pragma unroll
        for (int j = 0; j < 2; j++) {
#pragma unroll
            for (int t = 0; t < acc[i][j].num_elements; t++) {
                float x = acc[i][j].x[t];
                if (EPI == EPI_TANH) x = tanhf(x);
                else if (EPI == EPI_SIG) x = 1.f / (1.f + __expf(-x));
                acc[i][j].x[t] = x;
            }
            const int r0 = brow + wm * 64 + i * 16;
            const int c0 = bcol + wn * 32 + j * 16;
            if (r0 + 16 <= M && c0 + 16 <= N) {
                wmma::store_matrix_sync(C + (size_t)r0 * N + c0, acc[i][j], N,
                                        wmma::mem_row_major);
            } else if (r0 < M && c0 < N) {
                wmma::store_matrix_sync(patch, acc[i][j], 20, wmma::mem_row_major);
                __syncwarp();
#pragma unroll
                for (int t = 0; t < 8; t++) {
                    int e = lane + t * 32;
                    int rr = e >> 4, cc = e & 15;
                    if (r0 + rr < M && c0 + cc < N)
                        C[(size_t)(r0 + rr) * N + (c0 + cc)] = patch[rr * 20 + cc];
                }
                __syncwarp();
            }
        }
    }
}

// ---- host side ----

static constexpr int SMEM_NN = (2 * 128 * 40 + 2 * 32 * 136) * 4; // 75776 B
static constexpr int SMEM_NT = (2 * 128 * 40 + 2 * 128 * 40) * 4; // 81920 B

template <int EPI, bool BT>
static void launch(const GArgs& ga) {
    constexpr int SM = BT ? SMEM_NT : SMEM_NN;
    cudaFuncSetAttribute(mm_kernel<EPI, BT>,
                         cudaFuncAttributeMaxDynamicSharedMemorySize, SM);
    dim3 grid((ga.N + 127) / 128, (ga.M + 127) / 128, 4);
    mm_kernel<EPI, BT><<<grid, 256, SM>>>(ga);
}

extern "C" void kernel_launch(void* const* d_in, const int* in_sizes, int n_in,
                              void* d_out, int out_size)
{
    const float* omics1 = (const float*)d_in[0];
    const float* omics2 = (const float*)d_in[1];
    const float* adj[4] = {(const float*)d_in[2], (const float*)d_in[3],
                           (const float*)d_in[4], (const float*)d_in[5]};
    const float* W[4][3];
    for (int e = 0; e < 4; e++)
        for (int l = 0; l < 3; l++)
            W[e][l] = (const float*)d_in[6 + e * 3 + l];

    float* out = (float*)d_out;

    float *bA = nullptr, *bB = nullptr;
    cudaGetSymbolAddress((void**)&bA, g_bufA);
    cudaGetSymbolAddress((void**)&bB, g_bufB);
    float* bufA[4], *bufB[4];
    for (int e = 0; e < 4; e++) {
        bufA[e] = bA + (size_t)e * NS * ENC1;
        bufB[e] = bB + (size_t)e * NS * ENC1;
    }

    const float* xs[4] = {omics1, omics2, omics1, omics2};

    GArgs ga;

    // S1: h1 = tanh(x @ W1)            [3000,256]
    for (int e = 0; e < 4; e++) { ga.A[e] = xs[e]; ga.B[e] = W[e][0]; ga.C[e] = bufA[e]; }
    ga.M = NS; ga.N = 256; ga.K = NS;
    launch<EPI_TANH, false>(ga);

    // S2: z1 = adj @ h1                [3000,256]
    for (int e = 0; e < 4; e++) { ga.A[e] = adj[e]; ga.B[e] = bufA[e]; ga.C[e] = bufB[e]; }
    ga.M = NS; ga.N = 256; ga.K = NS;
    launch<EPI_NONE, false>(ga);

    // S3: h2 = tanh(z1 @ W2)           [3000,128]
    for (int e = 0; e < 4; e++) { ga.A[e] = bufB[e]; ga.B[e] = W[e][1]; ga.C[e] = bufA[e]; }
    ga.M = NS; ga.N = 128; ga.K = 256;
    launch<EPI_TANH, false>(ga);

    // S4: z2 = adj @ h2                [3000,128]
    for (int e = 0; e < 4; e++) { ga.A[e] = adj[e]; ga.B[e] = bufA[e]; ga.C[e] = bufB[e]; }
    ga.M = NS; ga.N = 128; ga.K = NS;
    launch<EPI_NONE, false>(ga);

    // S5: h3 = z2 @ W3                 [3000,64]
    for (int e = 0; e < 4; e++) { ga.A[e] = bufB[e]; ga.B[e] = W[e][2]; ga.C[e] = bufA[e]; }
    ga.M = NS; ga.N = 64; ga.K = 128;
    launch<EPI_NONE, false>(ga);

    // S6: z3 = adj @ h3                [3000,64]
    for (int e = 0; e < 4; e++) { ga.A[e] = adj[e]; ga.B[e] = bufA[e]; ga.C[e] = bufB[e]; }
    ga.M = NS; ga.N = 64; ga.K = NS;
    launch<EPI_NONE, false>(ga);

    // S7: out[e] = sigmoid(z3 @ z3^T)  [3000,3000]
    for (int e = 0; e < 4; e++) {
        ga.A[e] = bufB[e]; ga.B[e] = bufB[e];
        ga.C[e] = out + (size_t)e * NS * NS;
    }
    ga.M = NS; ga.N = NS; ga.K = 64;
    launch<EPI_SIG, true>(ga);
}

// round 6
// speedup vs baseline: 15.2561x; 2.4068x over previous
#include <cuda_runtime.h>
#include <cuda_bf16.h>
#include <mma.h>
#include <math.h>

using namespace nvcuda;

#define NS   3000
#define ENC1 256

// bf16 copies of inputs (one-time convert per launch) + ping-pong intermediates.
__device__ __nv_bfloat16 g_adj_bf[4][NS * NS];
__device__ __nv_bfloat16 g_x_bf[2][NS * NS];
__device__ __nv_bfloat16 g_w_bf[4][3][NS * ENC1];   // oversized; max layer is 3000x256
__device__ __nv_bfloat16 g_bufA[4][NS * ENC1];
__device__ __nv_bfloat16 g_bufB[4][NS * ENC1];

enum { EPI_NONE = 0, EPI_TANH = 1, EPI_SIG = 2 };

// ---------------- fp32 -> bf16 conversion (grouped, vectorized) ----------------
struct CArgs {
    const float* s[4];
    __nv_bfloat16* d[4];
    int n;   // elements, multiple of 4
};

__global__ void f2bf_kernel(CArgs ca)
{
    const float* __restrict__ s = ca.s[blockIdx.y];
    __nv_bfloat16* __restrict__ d = ca.d[blockIdx.y];
    const int n4 = ca.n >> 2;
    for (int i = blockIdx.x * blockDim.x + threadIdx.x; i < n4;
         i += gridDim.x * blockDim.x) {
        float4 v = ((const float4*)s)[i];
        ((__nv_bfloat162*)d)[2 * i]     = __floats2bfloat162_rn(v.x, v.y);
        ((__nv_bfloat162*)d)[2 * i + 1] = __floats2bfloat162_rn(v.z, v.w);
    }
}

// ---------------- async copy helpers ----------------
__device__ __forceinline__ void cp_async16(void* s, const void* g, bool pred) {
    unsigned saddr = (unsigned)__cvta_generic_to_shared(s);
    if (pred) {
        asm volatile("cp.async.cg.shared.global [%0], [%1], 16;\n"
                     :: "r"(saddr), "l"(g));
    } else {
        *(float4*)s = make_float4(0.f, 0.f, 0.f, 0.f);
    }
}
__device__ __forceinline__ void cp_commit() {
    asm volatile("cp.async.commit_group;\n");
}
template <int NMAX>
__device__ __forceinline__ void cp_wait() {
    asm volatile("cp.async.wait_group %0;\n" :: "n"(NMAX));
}

// ---------------- grouped bf16 GEMM ----------------
// C[g] = epi(A[g] @ B[g])     (BT=true: A[g] @ B[g]^T with B[g] stored [N,K])
// A,B bf16; C bf16 (OUTBF) or fp32. Block tile BM x 128 x 32, 8 warps,
// wmma m16n16k16 bf16, fp32 accum, double-buffered cp.async.
// Requires K%8==0, N%8==0 (all call sites). M,N edges guarded.
struct GArgs {
    const __nv_bfloat16* A[4];
    const __nv_bfloat16* B[4];
    void* C[4];
    int M, N, K;
};

template <int EPI, bool BT, int BM, bool OUTBF>
__global__ void __launch_bounds__(256, 2)
mm_bf16(GArgs ga)
{
    constexpr int BN = 128, BK = 32;
    constexpr int LDA = BK + 8;                    // 40 bf16 (80B rows)
    constexpr int LDB = BT ? (BK + 8) : (BN + 8);  // 40 or 136
    constexpr int ASZ = BM * LDA;
    constexpr int BSZ = BT ? BN * LDB : BK * LDB;
    constexpr int FM  = BM / 32;                   // frag rows per warp (4 or 2)

    extern __shared__ char smem_raw[];
    __nv_bfloat16* As = (__nv_bfloat16*)smem_raw;          // [2][ASZ]
    __nv_bfloat16* Bs = As + 2 * ASZ;                      // [2][BSZ]

    const int g = blockIdx.z;
    const __nv_bfloat16* __restrict__ A = ga.A[g];
    const __nv_bfloat16* __restrict__ B = ga.B[g];
    const int M = ga.M, N = ga.N, K = ga.K;

    const int tid  = threadIdx.x;
    const int wid  = tid >> 5;
    const int lane = tid & 31;
    const int wm = wid >> 2;       // 0..1
    const int wn = wid & 3;        // 0..3
    const int brow = blockIdx.y * BM;
    const int bcol = blockIdx.x * BN;

    wmma::fragment<wmma::accumulator, 16, 16, 16, float> acc[FM][2];
#pragma unroll
    for (int i = 0; i < FM; i++)
#pragma unroll
        for (int j = 0; j < 2; j++) wmma::fill_fragment(acc[i][j], 0.f);

    const int nkt = (K + BK - 1) / BK;

    auto load_tile = [&](int kt, int p) {
        const int k0 = kt * BK;
        // A: BM rows x 32 bf16 = 4 chunks(16B)/row
#pragma unroll
        for (int i = 0; i < BM / 64; i++) {
            int lin = tid + i * 256;
            int row = lin >> 2, c8 = (lin & 3) * 8;
            int gr = brow + row, gk = k0 + c8;
            cp_async16(As + p * ASZ + row * LDA + c8,
                       A + (size_t)gr * K + gk, (gr < M) && (gk < K));
        }
        if (!BT) {
            // B[K,N]: 32 k-rows x 128 n = 16 chunks/row
#pragma unroll
            for (int i = 0; i < 2; i++) {
                int lin = tid + i * 256;
                int kr = lin >> 4, c8 = (lin & 15) * 8;
                int gk = k0 + kr, gn = bcol + c8;
                cp_async16(Bs + p * BSZ + kr * LDB + c8,
                           B + (size_t)gk * N + gn, (gk < K) && (gn < N));
            }
        } else {
            // B[N,K]: 128 n-rows x 32 k
#pragma unroll
            for (int i = 0; i < 2; i++) {
                int lin = tid + i * 256;
                int nr = lin >> 2, c8 = (lin & 3) * 8;
                int gn = bcol + nr, gk = k0 + c8;
                cp_async16(Bs + p * BSZ + nr * LDB + c8,
                           B + (size_t)gn * K + gk, (gn < N) && (gk < K));
            }
        }
        cp_commit();
    };

    load_tile(0, 0);

    for (int kt = 0; kt < nkt; ++kt) {
        const int p = kt & 1;
        if (kt + 1 < nkt) {
            load_tile(kt + 1, p ^ 1);
            cp_wait<1>();
        } else {
            cp_wait<0>();
        }
        __syncthreads();

        __nv_bfloat16* as = As + p * ASZ + (wm * FM * 16) * LDA;
#pragma unroll
        for (int ks = 0; ks < 2; ks++) {
            wmma::fragment<wmma::matrix_a, 16, 16, 16, __nv_bfloat16,
                           wmma::row_major> af[FM];
#pragma unroll
            for (int i = 0; i < FM; i++)
                wmma::load_matrix_sync(af[i], as + (i * 16) * LDA + ks * 16, LDA);

            if (!BT) {
                wmma::fragment<wmma::matrix_b, 16, 16, 16, __nv_bfloat16,
                               wmma::row_major> bf[2];
                __nv_bfloat16* bs = Bs + p * BSZ + (ks * 16) * LDB + wn * 32;
#pragma unroll
                for (int j = 0; j < 2; j++)
                    wmma::load_matrix_sync(bf[j], bs + j * 16, LDB);
#pragma unroll
                for (int i = 0; i < FM; i++)
#pragma unroll
                    for (int j = 0; j < 2; j++)
                        wmma::mma_sync(acc[i][j], af[i], bf[j], acc[i][j]);
            } else {
                wmma::fragment<wmma::matrix_b, 16, 16, 16, __nv_bfloat16,
                               wmma::col_major> bf[2];
                __nv_bfloat16* bs = Bs + p * BSZ + (wn * 32) * LDB + ks * 16;
#pragma unroll
                for (int j = 0; j < 2; j++)
                    wmma::load_matrix_sync(bf[j], bs + (j * 16) * LDB, LDB);
#pragma unroll
                for (int i = 0; i < FM; i++)
#pragma unroll
                    for (int j = 0; j < 2; j++)
                        wmma::mma_sync(acc[i][j], af[i], bf[j], acc[i][j]);
            }
        }
        __syncthreads();
    }

    // ---- epilogue ----
    __syncthreads();                              // smem free for staging
    float* patch = (float*)smem_raw + wid * (16 * 20);

#pragma unroll
    for (int i = 0; i < FM; i++) {
#pragma unroll
        for (int j = 0; j < 2; j++) {
#pragma unroll
            for (int t = 0; t < acc[i][j].num_elements; t++) {
                float x = acc[i][j].x[t];
                if (EPI == EPI_TANH) x = tanhf(x);
                else if (EPI == EPI_SIG) x = 1.f / (1.f + __expf(-x));
                acc[i][j].x[t] = x;
            }
            const int r0 = brow + wm * FM * 16 + i * 16;
            const int c0 = bcol + wn * 32 + j * 16;
            if (r0 >= M || c0 >= N) continue;

            if (!OUTBF) {
                float* Cf = (float*)ga.C[g];
                if (r0 + 16 <= M && c0 + 16 <= N) {
                    wmma::store_matrix_sync(Cf + (size_t)r0 * N + c0, acc[i][j],
                                            N, wmma::mem_row_major);
                } else {
                    wmma::store_matrix_sync(patch, acc[i][j], 20,
                                            wmma::mem_row_major);
                    __syncwarp();
#pragma unroll
                    for (int t = 0; t < 8; t++) {
                        int e = lane + t * 32;
                        int rr = e >> 4, cc = e & 15;
                        if (r0 + rr < M && c0 + cc < N)
                            Cf[(size_t)(r0 + rr) * N + (c0 + cc)] =
                                patch[rr * 20 + cc];
                    }
                    __syncwarp();
                }
            } else {
                __nv_bfloat16* Cb = (__nv_bfloat16*)ga.C[g];
                wmma::store_matrix_sync(patch, acc[i][j], 20, wmma::mem_row_major);
                __syncwarp();
#pragma unroll
                for (int t = 0; t < 8; t++) {
                    int e = lane + t * 32;
                    int rr = e >> 4, cc = e & 15;
                    if (r0 + rr < M && c0 + cc < N)
                        Cb[(size_t)(r0 + rr) * N + (c0 + cc)] =
                            __float2bfloat16(patch[rr * 20 + cc]);
                }
                __syncwarp();
            }
        }
    }
}

// ---------------- host side ----------------
template <int EPI, bool BT, int BM, bool OUTBF>
static void launch(const GArgs& ga) {
    constexpr int LDA = 40, LDB = BT ? 40 : 136;
    constexpr int ASZ = BM * LDA;
    constexpr int BSZ = BT ? 128 * LDB : 32 * LDB;
    constexpr int SMB = 2 * (ASZ + BSZ) * 2;   // bytes
    cudaFuncSetAttribute(mm_bf16<EPI, BT, BM, OUTBF>,
                         cudaFuncAttributeMaxDynamicSharedMemorySize, SMB);
    dim3 grid((ga.N + 127) / 128, (ga.M + BM - 1) / BM, 4);
    mm_bf16<EPI, BT, BM, OUTBF><<<grid, 256, SMB>>>(ga);
}

extern "C" void kernel_launch(void* const* d_in, const int* in_sizes, int n_in,
                              void* d_out, int out_size)
{
    const float* omics[2] = {(const float*)d_in[0], (const float*)d_in[1]};
    const float* adj[4]   = {(const float*)d_in[2], (const float*)d_in[3],
                             (const float*)d_in[4], (const float*)d_in[5]};
    const float* W[4][3];
    for (int e = 0; e < 4; e++)
        for (int l = 0; l < 3; l++)
            W[e][l] = (const float*)d_in[6 + e * 3 + l];

    float* out = (float*)d_out;

    __nv_bfloat16 *adjB, *xB, *wB, *bA, *bB;
    cudaGetSymbolAddress((void**)&adjB, g_adj_bf);
    cudaGetSymbolAddress((void**)&xB, g_x_bf);
    cudaGetSymbolAddress((void**)&wB, g_w_bf);
    cudaGetSymbolAddress((void**)&bA, g_bufA);
    cudaGetSymbolAddress((void**)&bB, g_bufB);

    __nv_bfloat16* adj_bf[4];
    __nv_bfloat16* x_bf[2];
    __nv_bfloat16* w_bf[4][3];
    __nv_bfloat16 *bufA[4], *bufB[4];
    for (int e = 0; e < 4; e++) {
        adj_bf[e] = adjB + (size_t)e * NS * NS;
        for (int l = 0; l < 3; l++)
            w_bf[e][l] = wB + ((size_t)e * 3 + l) * NS * ENC1;
        bufA[e] = bA + (size_t)e * NS * ENC1;
        bufB[e] = bB + (size_t)e * NS * ENC1;
    }
    x_bf[0] = xB; x_bf[1] = xB + (size_t)NS * NS;

    // --- conversions ---
    CArgs ca;
    // adjacencies
    for (int e = 0; e < 4; e++) { ca.s[e] = adj[e]; ca.d[e] = adj_bf[e]; }
    ca.n = NS * NS;
    f2bf_kernel<<<dim3(1024, 4), 256>>>(ca);
    // omics
    for (int e = 0; e < 4; e++) { ca.s[e] = omics[e & 1]; ca.d[e] = x_bf[e & 1]; }
    ca.n = NS * NS;
    f2bf_kernel<<<dim3(1024, 2), 256>>>(ca);
    // weights, per layer
    const int wsz[3] = {NS * 256, 256 * 128, 128 * 64};
    for (int l = 0; l < 3; l++) {
        for (int e = 0; e < 4; e++) { ca.s[e] = W[e][l]; ca.d[e] = w_bf[e][l]; }
        ca.n = wsz[l];
        f2bf_kernel<<<dim3(256, 4), 256>>>(ca);
    }

    GArgs ga;

    // S1: h1 = tanh(x @ W1)   [3000,256]
    for (int e = 0; e < 4; e++) { ga.A[e] = x_bf[e & 1]; ga.B[e] = w_bf[e][0]; ga.C[e] = bufA[e]; }
    ga.M = NS; ga.N = 256; ga.K = NS;
    launch<EPI_TANH, false, 128, true>(ga);

    // S2: z1 = adj @ h1        [3000,256]
    for (int e = 0; e < 4; e++) { ga.A[e] = adj_bf[e]; ga.B[e] = bufA[e]; ga.C[e] = bufB[e]; }
    ga.M = NS; ga.N = 256; ga.K = NS;
    launch<EPI_NONE, false, 128, true>(ga);

    // S3: h2 = tanh(z1 @ W2)   [3000,128]
    for (int e = 0; e < 4; e++) { ga.A[e] = bufB[e]; ga.B[e] = w_bf[e][1]; ga.C[e] = bufA[e]; }
    ga.M = NS; ga.N = 128; ga.K = 256;
    launch<EPI_TANH, false, 64, true>(ga);

    // S4: z2 = adj @ h2        [3000,128]
    for (int e = 0; e < 4; e++) { ga.A[e] = adj_bf[e]; ga.B[e] = bufA[e]; ga.C[e] = bufB[e]; }
    ga.M = NS; ga.N = 128; ga.K = NS;
    launch<EPI_NONE, false, 64, true>(ga);

    // S5: h3 = z2 @ W3         [3000,64]
    for (int e = 0; e < 4; e++) { ga.A[e] = bufB[e]; ga.B[e] = w_bf[e][2]; ga.C[e] = bufA[e]; }
    ga.M = NS; ga.N = 64; ga.K = 128;
    launch<EPI_NONE, false, 64, true>(ga);

    // S6: z3 = adj @ h3        [3000,64]
    for (int e = 0; e < 4; e++) { ga.A[e] = adj_bf[e]; ga.B[e] = bufA[e]; ga.C[e] = bufB[e]; }
    ga.M = NS; ga.N = 64; ga.K = NS;
    launch<EPI_NONE, false, 64, true>(ga);

    // S7: out[e] = sigmoid(z3 @ z3^T)  [3000,3000] fp32
    for (int e = 0; e < 4; e++) {
        ga.A[e] = bufB[e]; ga.B[e] = bufB[e];
        ga.C[e] = out + (size_t)e * NS * NS;
    }
    ga.M = NS; ga.N = NS; ga.K = 64;
    launch<EPI_SIG, true, 128, false>(ga);
}

// round 14
// speedup vs baseline: 16.0626x; 1.0529x over previous
#include <cuda_runtime.h>
#include <cuda_bf16.h>
#include <mma.h>
#include <math.h>

using namespace nvcuda;

#define NS   3000
#define ENC1 256

// bf16 copies of inputs (one-time convert per launch) + ping-pong intermediates.
__device__ __align__(256) __nv_bfloat16 g_adj_bf[4][NS * NS];
__device__ __align__(256) __nv_bfloat16 g_x_bf[2][NS * NS];
__device__ __align__(256) __nv_bfloat16 g_w_bf[4][3][NS * ENC1];
__device__ __align__(256) __nv_bfloat16 g_bufA[4][NS * ENC1];
__device__ __align__(256) __nv_bfloat16 g_bufB[4][NS * ENC1];

enum { EPI_NONE = 0, EPI_TANH = 1, EPI_SIG = 2 };

// ---------------- fp32 -> bf16 conversion (grouped, vectorized) ----------------
struct CArgs {
    const float* s[4];
    __nv_bfloat16* d[4];
    int n;   // elements, multiple of 4
};

__global__ void f2bf_kernel(CArgs ca)
{
    const float* __restrict__ s = ca.s[blockIdx.y];
    __nv_bfloat16* __restrict__ d = ca.d[blockIdx.y];
    const int n4 = ca.n >> 2;
    for (int i = blockIdx.x * blockDim.x + threadIdx.x; i < n4;
         i += gridDim.x * blockDim.x) {
        float4 v = ((const float4*)s)[i];
        ((__nv_bfloat162*)d)[2 * i]     = __floats2bfloat162_rn(v.x, v.y);
        ((__nv_bfloat162*)d)[2 * i + 1] = __floats2bfloat162_rn(v.z, v.w);
    }
}

// ---------------- async copy helpers ----------------
__device__ __forceinline__ void cp_async16(void* s, const void* g, bool pred) {
    unsigned saddr = (unsigned)__cvta_generic_to_shared(s);
    if (pred) {
        asm volatile("cp.async.cg.shared.global [%0], [%1], 16;\n"
                     :: "r"(saddr), "l"(g));
    } else {
        *(float4*)s = make_float4(0.f, 0.f, 0.f, 0.f);
    }
}
__device__ __forceinline__ void cp_commit() {
    asm volatile("cp.async.commit_group;\n");
}
template <int NMAX>
__device__ __forceinline__ void cp_wait() {
    asm volatile("cp.async.wait_group %0;\n" :: "n"(NMAX));
}

// ---------------- grouped bf16 GEMM ----------------
// C[g] = epi(A[g] @ B[g])     (BT=true: A[g] @ B[g]^T with B[g] stored [N,K])
// A,B bf16; C bf16 (OUTBF) or fp32. Block tile BM x 128 x 32, 8 warps,
// wmma m16n16k16 bf16, fp32 accum, 3-stage cp.async pipeline,
// ONE __syncthreads per K-iteration (next-next load issued after compute).
struct GArgs {
    const __nv_bfloat16* A[4];
    const __nv_bfloat16* B[4];
    void* C[4];
    int M, N, K;
};

template <int EPI, bool BT, int BM, bool OUTBF>
__global__ void __launch_bounds__(256, 2)
mm_bf16(GArgs ga)
{
    constexpr int BN = 128, BK = 32;
    constexpr int LDA = BK + 8;                    // 40 bf16 (80B rows)
    constexpr int LDB = BT ? (BK + 8) : (BN + 8);  // 40 or 136
    constexpr int ASZ = BM * LDA;
    constexpr int BSZ = BT ? BN * LDB : BK * LDB;
    constexpr int FM  = BM / 32;                   // frag rows per warp (4 or 2)
    constexpr int NSTG = 3;

    extern __shared__ char smem_raw[];
    __nv_bfloat16* As = (__nv_bfloat16*)smem_raw;          // [NSTG][ASZ]
    __nv_bfloat16* Bs = As + NSTG * ASZ;                   // [NSTG][BSZ]

    const int g = blockIdx.z;
    const __nv_bfloat16* __restrict__ A = ga.A[g];
    const __nv_bfloat16* __restrict__ B = ga.B[g];
    const int M = ga.M, N = ga.N, K = ga.K;

    const int tid  = threadIdx.x;
    const int wid  = tid >> 5;
    const int lane = tid & 31;
    const int wm = wid >> 2;       // 0..1
    const int wn = wid & 3;        // 0..3
    const int brow = blockIdx.y * BM;
    const int bcol = blockIdx.x * BN;

    wmma::fragment<wmma::accumulator, 16, 16, 16, float> acc[FM][2];
#pragma unroll
    for (int i = 0; i < FM; i++)
#pragma unroll
        for (int j = 0; j < 2; j++) wmma::fill_fragment(acc[i][j], 0.f);

    const int nkt = (K + BK - 1) / BK;

    auto load_tile = [&](int kt, int p) {
        const int k0 = kt * BK;
        // A: BM rows x 32 bf16 = 4 chunks(16B)/row
#pragma unroll
        for (int i = 0; i < BM / 64; i++) {
            int lin = tid + i * 256;
            int row = lin >> 2, c8 = (lin & 3) * 8;
            int gr = brow + row, gk = k0 + c8;
            cp_async16(As + p * ASZ + row * LDA + c8,
                       A + (size_t)gr * K + gk, (gr < M) && (gk < K));
        }
        if (!BT) {
            // B[K,N]: 32 k-rows x 128 n = 16 chunks/row
#pragma unroll
            for (int i = 0; i < 2; i++) {
                int lin = tid + i * 256;
                int kr = lin >> 4, c8 = (lin & 15) * 8;
                int gk = k0 + kr, gn = bcol + c8;
                cp_async16(Bs + p * BSZ + kr * LDB + c8,
                           B + (size_t)gk * N + gn, (gk < K) && (gn < N));
            }
        } else {
            // B[N,K]: 128 n-rows x 32 k
#pragma unroll
            for (int i = 0; i < 2; i++) {
                int lin = tid + i * 256;
                int nr = lin >> 2, c8 = (lin & 3) * 8;
                int gn = bcol + nr, gk = k0 + c8;
                cp_async16(Bs + p * BSZ + nr * LDB + c8,
                           B + (size_t)gn * K + gk, (gn < N) && (gk < K));
            }
        }
        cp_commit();
    };

    // prologue: fill 2 pipeline stages
    load_tile(0, 0);
    if (nkt > 1) load_tile(1, 1);

    for (int kt = 0; kt < nkt; ++kt) {
        const int p = kt % NSTG;
        // buffer kt complete when <=1 newer group pending
        if (kt + 1 < nkt) cp_wait<1>(); else cp_wait<0>();
        __syncthreads();   // loads of buf p visible; all prior compute done

        __nv_bfloat16* as = As + p * ASZ + (wm * FM * 16) * LDA;
#pragma unroll
        for (int ks = 0; ks < 2; ks++) {
            wmma::fragment<wmma::matrix_a, 16, 16, 16, __nv_bfloat16,
                           wmma::row_major> af[FM];
#pragma unroll
            for (int i = 0; i < FM; i++)
                wmma::load_matrix_sync(af[i], as + (i * 16) * LDA + ks * 16, LDA);

            if (!BT) {
                wmma::fragment<wmma::matrix_b, 16, 16, 16, __nv_bfloat16,
                               wmma::row_major> bf[2];
                __nv_bfloat16* bs = Bs + p * BSZ + (ks * 16) * LDB + wn * 32;
#pragma unroll
                for (int j = 0; j < 2; j++)
                    wmma::load_matrix_sync(bf[j], bs + j * 16, LDB);
#pragma unroll
                for (int i = 0; i < FM; i++)
#pragma unroll
                    for (int j = 0; j < 2; j++)
                        wmma::mma_sync(acc[i][j], af[i], bf[j], acc[i][j]);
            } else {
                wmma::fragment<wmma::matrix_b, 16, 16, 16, __nv_bfloat16,
                               wmma::col_major> bf[2];
                __nv_bfloat16* bs = Bs + p * BSZ + (wn * 32) * LDB + ks * 16;
#pragma unroll
                for (int j = 0; j < 2; j++)
                    wmma::load_matrix_sync(bf[j], bs + (j * 16) * LDB, LDB);
#pragma unroll
                for (int i = 0; i < FM; i++)
#pragma unroll
                    for (int j = 0; j < 2; j++)
                        wmma::mma_sync(acc[i][j], af[i], bf[j], acc[i][j]);
            }
        }

        // issue load for kt+2 into buffer (kt+2)%3 — that buffer was computed
        // at kt-1, and sync(kt) above ordered all threads past that compute.
        if (kt + 2 < nkt) load_tile(kt + 2, (kt + 2) % NSTG);
    }

    // ---- epilogue ----
    __syncthreads();                              // smem free for staging
    float* patch = (float*)smem_raw + wid * (16 * 20);

#pragma unroll
    for (int i = 0; i < FM; i++) {
#pragma unroll
        for (int j = 0; j < 2; j++) {
#pragma unroll
            for (int t = 0; t < acc[i][j].num_elements; t++) {
                float x = acc[i][j].x[t];
                if (EPI == EPI_TANH) x = tanhf(x);
                else if (EPI == EPI_SIG) x = 1.f / (1.f + __expf(-x));
                acc[i][j].x[t] = x;
            }
            const int r0 = brow + wm * FM * 16 + i * 16;
            const int c0 = bcol + wn * 32 + j * 16;
            if (r0 >= M || c0 >= N) continue;

            if (!OUTBF) {
                float* Cf = (float*)ga.C[g];
                if (r0 + 16 <= M && c0 + 16 <= N) {
                    wmma::store_matrix_sync(Cf + (size_t)r0 * N + c0, acc[i][j],
                                            N, wmma::mem_row_major);
                } else {
                    wmma::store_matrix_sync(patch, acc[i][j], 20,
                                            wmma::mem_row_major);
                    __syncwarp();
#pragma unroll
                    for (int t = 0; t < 8; t++) {
                        int e = lane + t * 32;
                        int rr = e >> 4, cc = e & 15;
                        if (r0 + rr < M && c0 + cc < N)
                            Cf[(size_t)(r0 + rr) * N + (c0 + cc)] =
                                patch[rr * 20 + cc];
                    }
                    __syncwarp();
                }
            } else {
                __nv_bfloat16* Cb = (__nv_bfloat16*)ga.C[g];
                wmma::store_matrix_sync(patch, acc[i][j], 20, wmma::mem_row_major);
                __syncwarp();
#pragma unroll
                for (int t = 0; t < 8; t++) {
                    int e = lane + t * 32;
                    int rr = e >> 4, cc = e & 15;
                    if (r0 + rr < M && c0 + cc < N)
                        Cb[(size_t)(r0 + rr) * N + (c0 + cc)] =
                            __float2bfloat16(patch[rr * 20 + cc]);
                }
                __syncwarp();
            }
        }
    }
}

// ---------------- host side ----------------
template <int EPI, bool BT, int BM, bool OUTBF>
static void launch(const GArgs& ga) {
    constexpr int LDA = 40, LDB = BT ? 40 : 136;
    constexpr int ASZ = BM * LDA;
    constexpr int BSZ = BT ? 128 * LDB : 32 * LDB;
    constexpr int SMB = 3 * (ASZ + BSZ) * 2;   // bytes (3 pipeline stages)
    cudaFuncSetAttribute(mm_bf16<EPI, BT, BM, OUTBF>,
                         cudaFuncAttributeMaxDynamicSharedMemorySize, SMB);
    dim3 grid((ga.N + 127) / 128, (ga.M + BM - 1) / BM, 4);
    mm_bf16<EPI, BT, BM, OUTBF><<<grid, 256, SMB>>>(ga);
}

extern "C" void kernel_launch(void* const* d_in, const int* in_sizes, int n_in,
                              void* d_out, int out_size)
{
    const float* omics[2] = {(const float*)d_in[0], (const float*)d_in[1]};
    const float* adj[4]   = {(const float*)d_in[2], (const float*)d_in[3],
                             (const float*)d_in[4], (const float*)d_in[5]};
    const float* W[4][3];
    for (int e = 0; e < 4; e++)
        for (int l = 0; l < 3; l++)
            W[e][l] = (const float*)d_in[6 + e * 3 + l];

    float* out = (float*)d_out;

    __nv_bfloat16 *adjB, *xB, *wB, *bA, *bB;
    cudaGetSymbolAddress((void**)&adjB, g_adj_bf);
    cudaGetSymbolAddress((void**)&xB, g_x_bf);
    cudaGetSymbolAddress((void**)&wB, g_w_bf);
    cudaGetSymbolAddress((void**)&bA, g_bufA);
    cudaGetSymbolAddress((void**)&bB, g_bufB);

    __nv_bfloat16* adj_bf[4];
    __nv_bfloat16* x_bf[2];
    __nv_bfloat16* w_bf[4][3];
    __nv_bfloat16 *bufA[4], *bufB[4];
    for (int e = 0; e < 4; e++) {
        adj_bf[e] = adjB + (size_t)e * NS * NS;
        for (int l = 0; l < 3; l++)
            w_bf[e][l] = wB + ((size_t)e * 3 + l) * NS * ENC1;
        bufA[e] = bA + (size_t)e * NS * ENC1;
        bufB[e] = bB + (size_t)e * NS * ENC1;
    }
    x_bf[0] = xB; x_bf[1] = xB + (size_t)NS * NS;

    // --- conversions ---
    CArgs ca;
    for (int e = 0; e < 4; e++) { ca.s[e] = adj[e]; ca.d[e] = adj_bf[e]; }
    ca.n = NS * NS;
    f2bf_kernel<<<dim3(1024, 4), 256>>>(ca);
    for (int e = 0; e < 2; e++) { ca.s[e] = omics[e]; ca.d[e] = x_bf[e]; }
    ca.n = NS * NS;
    f2bf_kernel<<<dim3(1024, 2), 256>>>(ca);
    const int wsz[3] = {NS * 256, 256 * 128, 128 * 64};
    for (int l = 0; l < 3; l++) {
        for (int e = 0; e < 4; e++) { ca.s[e] = W[e][l]; ca.d[e] = w_bf[e][l]; }
        ca.n = wsz[l];
        f2bf_kernel<<<dim3(256, 4), 256>>>(ca);
    }

    GArgs ga;

    // S1: h1 = tanh(x @ W1)   [3000,256]
    for (int e = 0; e < 4; e++) { ga.A[e] = x_bf[e & 1]; ga.B[e] = w_bf[e][0]; ga.C[e] = bufA[e]; }
    ga.M = NS; ga.N = 256; ga.K = NS;
    launch<EPI_TANH, false, 128, true>(ga);

    // S2: z1 = adj @ h1        [3000,256]
    for (int e = 0; e < 4; e++) { ga.A[e] = adj_bf[e]; ga.B[e] = bufA[e]; ga.C[e] = bufB[e]; }
    ga.M = NS; ga.N = 256; ga.K = NS;
    launch<EPI_NONE, false, 128, true>(ga);

    // S3: h2 = tanh(z1 @ W2)   [3000,128]
    for (int e = 0; e < 4; e++) { ga.A[e] = bufB[e]; ga.B[e] = w_bf[e][1]; ga.C[e] = bufA[e]; }
    ga.M = NS; ga.N = 128; ga.K = 256;
    launch<EPI_TANH, false, 64, true>(ga);

    // S4: z2 = adj @ h2        [3000,128]
    for (int e = 0; e < 4; e++) { ga.A[e] = adj_bf[e]; ga.B[e] = bufA[e]; ga.C[e] = bufB[e]; }
    ga.M = NS; ga.N = 128; ga.K = NS;
    launch<EPI_NONE, false, 64, true>(ga);

    // S5: h3 = z2 @ W3         [3000,64]
    for (int e = 0; e < 4; e++) { ga.A[e] = bufB[e]; ga.B[e] = w_bf[e][2]; ga.C[e] = bufA[e]; }
    ga.M = NS; ga.N = 64; ga.K = 128;
    launch<EPI_NONE, false, 64, true>(ga);

    // S6: z3 = adj @ h3        [3000,64]
    for (int e = 0; e < 4; e++) { ga.A[e] = adj_bf[e]; ga.B[e] = bufA[e]; ga.C[e] = bufB[e]; }
    ga.M = NS; ga.N = 64; ga.K = NS;
    launch<EPI_NONE, false, 64, true>(ga);

    // S7: out[e] = sigmoid(z3 @ z3^T)  [3000,3000] fp32
    for (int e = 0; e < 4; e++) {
        ga.A[e] = bufB[e]; ga.B[e] = bufB[e];
        ga.C[e] = out + (size_t)e * NS * NS;
    }
    ga.M = NS; ga.N = NS; ga.K = 64;
    launch<EPI_SIG, true, 128, false>(ga);
}

// round 15
// speedup vs baseline: 16.4243x; 1.0225x over previous
#include <cuda_runtime.h>
#include <cuda_bf16.h>
#include <mma.h>
#include <math.h>

using namespace nvcuda;

#define NS   3000
#define ENC1 256

// bf16 copies of inputs (one-time convert per launch) + ping-pong intermediates.
__device__ __align__(256) __nv_bfloat16 g_adj_bf[4][NS * NS];
__device__ __align__(256) __nv_bfloat16 g_x_bf[2][NS * NS];
__device__ __align__(256) __nv_bfloat16 g_w_bf[4][3][NS * ENC1];
__device__ __align__(256) __nv_bfloat16 g_bufA[4][NS * ENC1];
__device__ __align__(256) __nv_bfloat16 g_bufB[4][NS * ENC1];

enum { EPI_NONE = 0, EPI_TANH = 1, EPI_SIG = 2 };

// ---------------- fp32 -> bf16 conversion (grouped, vectorized) ----------------
struct CArgs {
    const float* s[4];
    __nv_bfloat16* d[4];
    int n;   // elements, multiple of 4
};

__global__ void f2bf_kernel(CArgs ca)
{
    const float* __restrict__ s = ca.s[blockIdx.y];
    __nv_bfloat16* __restrict__ d = ca.d[blockIdx.y];
    const int n4 = ca.n >> 2;
    for (int i = blockIdx.x * blockDim.x + threadIdx.x; i < n4;
         i += gridDim.x * blockDim.x) {
        float4 v = ((const float4*)s)[i];
        ((__nv_bfloat162*)d)[2 * i]     = __floats2bfloat162_rn(v.x, v.y);
        ((__nv_bfloat162*)d)[2 * i + 1] = __floats2bfloat162_rn(v.z, v.w);
    }
}

// ---------------- async copy helpers ----------------
__device__ __forceinline__ void cp_async16(void* s, const void* g, bool pred) {
    unsigned saddr = (unsigned)__cvta_generic_to_shared(s);
    if (pred) {
        asm volatile("cp.async.cg.shared.global [%0], [%1], 16;\n"
                     :: "r"(saddr), "l"(g));
    } else {
        *(float4*)s = make_float4(0.f, 0.f, 0.f, 0.f);
    }
}
__device__ __forceinline__ void cp_commit() {
    asm volatile("cp.async.commit_group;\n");
}
template <int NMAX>
__device__ __forceinline__ void cp_wait() {
    asm volatile("cp.async.wait_group %0;\n" :: "n"(NMAX));
}

// ---------------- grouped bf16 GEMM ----------------
// C[g] = epi(A[g] @ B[g])     (BT=true: A[g] @ B[g]^T with B[g] stored [N,K])
// Block tile BM x 128 x 32 (BM in {32,96,128}), 8 warps (2 x 4),
// warp tile (BM/2) x 32, wmma m16n16k16 bf16 fp32-accum,
// 3-stage cp.async pipeline, one __syncthreads per K-iteration.
struct GArgs {
    const __nv_bfloat16* A[4];
    const __nv_bfloat16* B[4];
    void* C[4];
    int M, N, K;
};

template <int EPI, bool BT, int BM, bool OUTBF>
__global__ void __launch_bounds__(256, 2)
mm_bf16(GArgs ga)
{
    constexpr int BN = 128, BK = 32;
    constexpr int LDA = BK + 8;                    // 40 bf16 (80B rows)
    constexpr int LDB = BT ? (BK + 8) : (BN + 8);  // 40 or 136
    constexpr int ASZ = BM * LDA;
    constexpr int BSZ = BT ? BN * LDB : BK * LDB;
    constexpr int FM  = BM / 32;                   // frag rows per warp
    constexpr int NSTG = 3;

    extern __shared__ char smem_raw[];
    __nv_bfloat16* As = (__nv_bfloat16*)smem_raw;          // [NSTG][ASZ]
    __nv_bfloat16* Bs = As + NSTG * ASZ;                   // [NSTG][BSZ]

    const int g = blockIdx.z;
    const __nv_bfloat16* __restrict__ A = ga.A[g];
    const __nv_bfloat16* __restrict__ B = ga.B[g];
    const int M = ga.M, N = ga.N, K = ga.K;

    const int tid  = threadIdx.x;
    const int wid  = tid >> 5;
    const int lane = tid & 31;
    const int wm = wid >> 2;       // 0..1
    const int wn = wid & 3;        // 0..3
    const int brow = blockIdx.y * BM;
    const int bcol = blockIdx.x * BN;

    wmma::fragment<wmma::accumulator, 16, 16, 16, float> acc[FM][2];
#pragma unroll
    for (int i = 0; i < FM; i++)
#pragma unroll
        for (int j = 0; j < 2; j++) wmma::fill_fragment(acc[i][j], 0.f);

    const int nkt = (K + BK - 1) / BK;

    auto load_tile = [&](int kt, int p) {
        const int k0 = kt * BK;
        // A: BM rows x 32 bf16 = BM*4 16B-chunks
        constexpr int ACH = BM * 4;
#pragma unroll
        for (int i = 0; i < (ACH + 255) / 256; i++) {
            int lin = tid + i * 256;
            if (ACH % 256 != 0 && lin >= ACH) break;
            int row = lin >> 2, c8 = (lin & 3) * 8;
            int gr = brow + row, gk = k0 + c8;
            cp_async16(As + p * ASZ + row * LDA + c8,
                       A + (size_t)gr * K + gk, (gr < M) && (gk < K));
        }
        if (!BT) {
            // B[K,N]: 32 k-rows x 128 n = 512 chunks
#pragma unroll
            for (int i = 0; i < 2; i++) {
                int lin = tid + i * 256;
                int kr = lin >> 4, c8 = (lin & 15) * 8;
                int gk = k0 + kr, gn = bcol + c8;
                cp_async16(Bs + p * BSZ + kr * LDB + c8,
                           B + (size_t)gk * N + gn, (gk < K) && (gn < N));
            }
        } else {
            // B[N,K]: 128 n-rows x 32 k = 512 chunks
#pragma unroll
            for (int i = 0; i < 2; i++) {
                int lin = tid + i * 256;
                int nr = lin >> 2, c8 = (lin & 3) * 8;
                int gn = bcol + nr, gk = k0 + c8;
                cp_async16(Bs + p * BSZ + nr * LDB + c8,
                           B + (size_t)gn * K + gk, (gn < N) && (gk < K));
            }
        }
        cp_commit();
    };

    // prologue: fill 2 pipeline stages
    load_tile(0, 0);
    if (nkt > 1) load_tile(1, 1);

    for (int kt = 0; kt < nkt; ++kt) {
        const int p = kt % NSTG;
        if (kt + 1 < nkt) cp_wait<1>(); else cp_wait<0>();
        __syncthreads();   // loads of buf p visible; all prior compute done

        __nv_bfloat16* as = As + p * ASZ + (wm * FM * 16) * LDA;
#pragma unroll
        for (int ks = 0; ks < 2; ks++) {
            wmma::fragment<wmma::matrix_a, 16, 16, 16, __nv_bfloat16,
                           wmma::row_major> af[FM];
#pragma unroll
            for (int i = 0; i < FM; i++)
                wmma::load_matrix_sync(af[i], as + (i * 16) * LDA + ks * 16, LDA);

            if (!BT) {
                wmma::fragment<wmma::matrix_b, 16, 16, 16, __nv_bfloat16,
                               wmma::row_major> bf[2];
                __nv_bfloat16* bs = Bs + p * BSZ + (ks * 16) * LDB + wn * 32;
#pragma unroll
                for (int j = 0; j < 2; j++)
                    wmma::load_matrix_sync(bf[j], bs + j * 16, LDB);
#pragma unroll
                for (int i = 0; i < FM; i++)
#pragma unroll
                    for (int j = 0; j < 2; j++)
                        wmma::mma_sync(acc[i][j], af[i], bf[j], acc[i][j]);
            } else {
                wmma::fragment<wmma::matrix_b, 16, 16, 16, __nv_bfloat16,
                               wmma::col_major> bf[2];
                __nv_bfloat16* bs = Bs + p * BSZ + (wn * 32) * LDB + ks * 16;
#pragma unroll
                for (int j = 0; j < 2; j++)
                    wmma::load_matrix_sync(bf[j], bs + (j * 16) * LDB, LDB);
#pragma unroll
                for (int i = 0; i < FM; i++)
#pragma unroll
                    for (int j = 0; j < 2; j++)
                        wmma::mma_sync(acc[i][j], af[i], bf[j], acc[i][j]);
            }
        }

        if (kt + 2 < nkt) load_tile(kt + 2, (kt + 2) % NSTG);
    }

    // ---- epilogue ----
    __syncthreads();                              // smem free for staging
    float* patch = (float*)smem_raw + wid * (16 * 20);

#pragma unroll
    for (int i = 0; i < FM; i++) {
#pragma unroll
        for (int j = 0; j < 2; j++) {
#pragma unroll
            for (int t = 0; t < acc[i][j].num_elements; t++) {
                float x = acc[i][j].x[t];
                if (EPI == EPI_TANH) x = tanhf(x);
                else if (EPI == EPI_SIG) x = 1.f / (1.f + __expf(-x));
                acc[i][j].x[t] = x;
            }
            const int r0 = brow + wm * FM * 16 + i * 16;
            const int c0 = bcol + wn * 32 + j * 16;
            if (r0 >= M || c0 >= N) continue;

            if (!OUTBF) {
                float* Cf = (float*)ga.C[g];
                if (r0 + 16 <= M && c0 + 16 <= N) {
                    wmma::store_matrix_sync(Cf + (size_t)r0 * N + c0, acc[i][j],
                                            N, wmma::mem_row_major);
                } else {
                    wmma::store_matrix_sync(patch, acc[i][j], 20,
                                            wmma::mem_row_major);
                    __syncwarp();
#pragma unroll
                    for (int t = 0; t < 8; t++) {
                        int e = lane + t * 32;
                        int rr = e >> 4, cc = e & 15;
                        if (r0 + rr < M && c0 + cc < N)
                            Cf[(size_t)(r0 + rr) * N + (c0 + cc)] =
                                patch[rr * 20 + cc];
                    }
                    __syncwarp();
                }
            } else {
                __nv_bfloat16* Cb = (__nv_bfloat16*)ga.C[g];
                wmma::store_matrix_sync(patch, acc[i][j], 20, wmma::mem_row_major);
                __syncwarp();
#pragma unroll
                for (int t = 0; t < 8; t++) {
                    int e = lane + t * 32;
                    int rr = e >> 4, cc = e & 15;
                    if (r0 + rr < M && c0 + cc < N)
                        Cb[(size_t)(r0 + rr) * N + (c0 + cc)] =
                            __float2bfloat16(patch[rr * 20 + cc]);
                }
                __syncwarp();
            }
        }
    }
}

// ---------------- host side ----------------
template <int EPI, bool BT, int BM, bool OUTBF>
static void launch(const GArgs& ga) {
    constexpr int LDA = 40, LDB = BT ? 40 : 136;
    constexpr int ASZ = BM * LDA;
    constexpr int BSZ = BT ? 128 * LDB : 32 * LDB;
    constexpr int SMB = 3 * (ASZ + BSZ) * 2;   // bytes (3 pipeline stages)
    cudaFuncSetAttribute(mm_bf16<EPI, BT, BM, OUTBF>,
                         cudaFuncAttributeMaxDynamicSharedMemorySize, SMB);
    dim3 grid((ga.N + 127) / 128, (ga.M + BM - 1) / BM, 4);
    mm_bf16<EPI, BT, BM, OUTBF><<<grid, 256, SMB>>>(ga);
}

extern "C" void kernel_launch(void* const* d_in, const int* in_sizes, int n_in,
                              void* d_out, int out_size)
{
    const float* omics[2] = {(const float*)d_in[0], (const float*)d_in[1]};
    const float* adj[4]   = {(const float*)d_in[2], (const float*)d_in[3],
                             (const float*)d_in[4], (const float*)d_in[5]};
    const float* W[4][3];
    for (int e = 0; e < 4; e++)
        for (int l = 0; l < 3; l++)
            W[e][l] = (const float*)d_in[6 + e * 3 + l];

    float* out = (float*)d_out;

    __nv_bfloat16 *adjB, *xB, *wB, *bA, *bB;
    cudaGetSymbolAddress((void**)&adjB, g_adj_bf);
    cudaGetSymbolAddress((void**)&xB, g_x_bf);
    cudaGetSymbolAddress((void**)&wB, g_w_bf);
    cudaGetSymbolAddress((void**)&bA, g_bufA);
    cudaGetSymbolAddress((void**)&bB, g_bufB);

    __nv_bfloat16* adj_bf[4];
    __nv_bfloat16* x_bf[2];
    __nv_bfloat16* w_bf[4][3];
    __nv_bfloat16 *bufA[4], *bufB[4];
    for (int e = 0; e < 4; e++) {
        adj_bf[e] = adjB + (size_t)e * NS * NS;
        for (int l = 0; l < 3; l++)
            w_bf[e][l] = wB + ((size_t)e * 3 + l) * NS * ENC1;
        bufA[e] = bA + (size_t)e * NS * ENC1;
        bufB[e] = bB + (size_t)e * NS * ENC1;
    }
    x_bf[0] = xB; x_bf[1] = xB + (size_t)NS * NS;

    // --- conversions ---
    CArgs ca;
    for (int e = 0; e < 4; e++) { ca.s[e] = adj[e]; ca.d[e] = adj_bf[e]; }
    ca.n = NS * NS;
    f2bf_kernel<<<dim3(1024, 4), 256>>>(ca);
    for (int e = 0; e < 2; e++) { ca.s[e] = omics[e]; ca.d[e] = x_bf[e]; }
    ca.n = NS * NS;
    f2bf_kernel<<<dim3(1024, 2), 256>>>(ca);
    const int wsz[3] = {NS * 256, 256 * 128, 128 * 64};
    for (int l = 0; l < 3; l++) {
        for (int e = 0; e < 4; e++) { ca.s[e] = W[e][l]; ca.d[e] = w_bf[e][l]; }
        ca.n = wsz[l];
        f2bf_kernel<<<dim3(256, 4), 256>>>(ca);
    }

    GArgs ga;

    // S1: h1 = tanh(x @ W1)   [3000,256]  grid 2x32x4=256 CTAs (86% balance)
    for (int e = 0; e < 4; e++) { ga.A[e] = x_bf[e & 1]; ga.B[e] = w_bf[e][0]; ga.C[e] = bufA[e]; }
    ga.M = NS; ga.N = 256; ga.K = NS;
    launch<EPI_TANH, false, 96, true>(ga);

    // S2: z1 = adj @ h1        [3000,256]
    for (int e = 0; e < 4; e++) { ga.A[e] = adj_bf[e]; ga.B[e] = bufA[e]; ga.C[e] = bufB[e]; }
    ga.M = NS; ga.N = 256; ga.K = NS;
    launch<EPI_NONE, false, 96, true>(ga);

    // S3: h2 = tanh(z1 @ W2)   [3000,128]  grid 1x94x4=376 CTAs
    for (int e = 0; e < 4; e++) { ga.A[e] = bufB[e]; ga.B[e] = w_bf[e][1]; ga.C[e] = bufA[e]; }
    ga.M = NS; ga.N = 128; ga.K = 256;
    launch<EPI_TANH, false, 32, true>(ga);

    // S4: z2 = adj @ h2        [3000,128]
    for (int e = 0; e < 4; e++) { ga.A[e] = adj_bf[e]; ga.B[e] = bufA[e]; ga.C[e] = bufB[e]; }
    ga.M = NS; ga.N = 128; ga.K = NS;
    launch<EPI_NONE, false, 32, true>(ga);

    // S5: h3 = z2 @ W3         [3000,64]
    for (int e = 0; e < 4; e++) { ga.A[e] = bufB[e]; ga.B[e] = w_bf[e][2]; ga.C[e] = bufA[e]; }
    ga.M = NS; ga.N = 64; ga.K = 128;
    launch<EPI_NONE, false, 32, true>(ga);

    // S6: z3 = adj @ h3        [3000,64]
    for (int e = 0; e < 4; e++) { ga.A[e] = adj_bf[e]; ga.B[e] = bufA[e]; ga.C[e] = bufB[e]; }
    ga.M = NS; ga.N = 64; ga.K = NS;
    launch<EPI_NONE, false, 32, true>(ga);

    // S7: out[e] = sigmoid(z3 @ z3^T)  [3000,3000] fp32  (2304 CTAs, well-waved)
    for (int e = 0; e < 4; e++) {
        ga.A[e] = bufB[e]; ga.B[e] = bufB[e];
        ga.C[e] = out + (size_t)e * NS * NS;
    }
    ga.M = NS; ga.N = NS; ga.K = 64;
    launch<EPI_SIG, true, 128, false>(ga);
}

// round 16
// speedup vs baseline: 17.5105x; 1.0661x over previous
#include <cuda_runtime.h>
#include <cuda_bf16.h>
#include <mma.h>
#include <math.h>

using namespace nvcuda;

#define NS   3000
#define ENC1 256

__device__ __align__(256) __nv_bfloat16 g_adj_bf[4][NS * NS];
__device__ __align__(256) __nv_bfloat16 g_x_bf[2][NS * NS];
__device__ __align__(256) __nv_bfloat16 g_w_bf[4][3][NS * ENC1];
__device__ __align__(256) __nv_bfloat16 g_bufA[4][NS * ENC1];
__device__ __align__(256) __nv_bfloat16 g_bufB[4][NS * ENC1];

enum { EPI_NONE = 0, EPI_TANH = 1, EPI_SIG = 2 };

// ---------------- fp32 -> bf16 conversions (2 launches total) ----------------
struct C6 { const float* s[6]; __nv_bfloat16* d[6]; int n; };

__global__ void f2bf6_kernel(C6 ca)
{
    const float* __restrict__ s = ca.s[blockIdx.y];
    __nv_bfloat16* __restrict__ d = ca.d[blockIdx.y];
    const int n4 = ca.n >> 2;
    for (int i = blockIdx.x * blockDim.x + threadIdx.x; i < n4;
         i += gridDim.x * blockDim.x) {
        float4 v = ((const float4*)s)[i];
        ((__nv_bfloat162*)d)[2 * i]     = __floats2bfloat162_rn(v.x, v.y);
        ((__nv_bfloat162*)d)[2 * i + 1] = __floats2bfloat162_rn(v.z, v.w);
    }
}

struct CW { const float* s[12]; __nv_bfloat16* d[12]; int n[12]; };

__global__ void f2bfw_kernel(CW ca)
{
    const float* __restrict__ s = ca.s[blockIdx.y];
    __nv_bfloat16* __restrict__ d = ca.d[blockIdx.y];
    const int n4 = ca.n[blockIdx.y] >> 2;
    for (int i = blockIdx.x * blockDim.x + threadIdx.x; i < n4;
         i += gridDim.x * blockDim.x) {
        float4 v = ((const float4*)s)[i];
        ((__nv_bfloat162*)d)[2 * i]     = __floats2bfloat162_rn(v.x, v.y);
        ((__nv_bfloat162*)d)[2 * i + 1] = __floats2bfloat162_rn(v.z, v.w);
    }
}

// ---------------- async copy helpers ----------------
__device__ __forceinline__ void cp_async16(void* s, const void* g, bool pred) {
    unsigned saddr = (unsigned)__cvta_generic_to_shared(s);
    if (pred) {
        asm volatile("cp.async.cg.shared.global [%0], [%1], 16;\n"
                     :: "r"(saddr), "l"(g));
    } else {
        *(float4*)s = make_float4(0.f, 0.f, 0.f, 0.f);
    }
}
__device__ __forceinline__ void cp_commit() {
    asm volatile("cp.async.commit_group;\n");
}
template <int NMAX>
__device__ __forceinline__ void cp_wait() {
    asm volatile("cp.async.wait_group %0;\n" :: "n"(NMAX));
}

// ---------------- grouped bf16 GEMM ----------------
// C[g] = epi(A[g] @ B[g])   (BT=true: A @ B^T, B stored [N,K])
// Block tile BM x 128 x 64, 8 warps (2 x 4), warp tile (BM/2) x 32,
// wmma m16n16k16 bf16 fp32-accum, 3-stage cp.async ring,
// one __syncthreads per K-iteration (kt+2 load issued after compute).
struct GArgs {
    const __nv_bfloat16* A[4];
    const __nv_bfloat16* B[4];
    void* C[4];
    int M, N, K;
};

template <int EPI, bool BT, int BM, bool OUTBF>
__global__ void __launch_bounds__(256, 2)
mm_bf16(GArgs ga)
{
    constexpr int BN = 128, BK = 64;
    constexpr int LDA = BK + 8;                    // 72 bf16 (144B rows)
    constexpr int LDB = BT ? (BK + 8) : (BN + 8);  // 72 or 136
    constexpr int ASZ = BM * LDA;
    constexpr int BSZ = BT ? BN * LDB : BK * LDB;
    constexpr int FM  = BM / 32;                   // frag rows per warp
    constexpr int NSTG = 3;

    extern __shared__ char smem_raw[];
    __nv_bfloat16* As = (__nv_bfloat16*)smem_raw;          // [NSTG][ASZ]
    __nv_bfloat16* Bs = As + NSTG * ASZ;                   // [NSTG][BSZ]

    const int g = blockIdx.z;
    const __nv_bfloat16* __restrict__ A = ga.A[g];
    const __nv_bfloat16* __restrict__ B = ga.B[g];
    const int M = ga.M, N = ga.N, K = ga.K;

    const int tid  = threadIdx.x;
    const int wid  = tid >> 5;
    const int lane = tid & 31;
    const int wm = wid >> 2;       // 0..1
    const int wn = wid & 3;        // 0..3
    const int brow = blockIdx.y * BM;
    const int bcol = blockIdx.x * BN;

    wmma::fragment<wmma::accumulator, 16, 16, 16, float> acc[FM][2];
#pragma unroll
    for (int i = 0; i < FM; i++)
#pragma unroll
        for (int j = 0; j < 2; j++) wmma::fill_fragment(acc[i][j], 0.f);

    const int nkt = (K + BK - 1) / BK;

    auto load_tile = [&](int kt, int p) {
        const int k0 = kt * BK;
        // A: BM rows x 64 bf16 = BM*8 16B-chunks
        constexpr int ACH = BM * 8;
#pragma unroll
        for (int i = 0; i < ACH / 256; i++) {
            int lin = tid + i * 256;
            int row = lin >> 3, c8 = (lin & 7) * 8;
            int gr = brow + row, gk = k0 + c8;
            cp_async16(As + p * ASZ + row * LDA + c8,
                       A + (size_t)gr * K + gk, (gr < M) && (gk < K));
        }
        if (!BT) {
            // B[K,N]: 64 k-rows x 128 n = 1024 chunks
#pragma unroll
            for (int i = 0; i < 4; i++) {
                int lin = tid + i * 256;
                int kr = lin >> 4, c8 = (lin & 15) * 8;
                int gk = k0 + kr, gn = bcol + c8;
                cp_async16(Bs + p * BSZ + kr * LDB + c8,
                           B + (size_t)gk * N + gn, (gk < K) && (gn < N));
            }
        } else {
            // B[N,K]: 128 n-rows x 64 k = 1024 chunks
#pragma unroll
            for (int i = 0; i < 4; i++) {
                int lin = tid + i * 256;
                int nr = lin >> 3, c8 = (lin & 7) * 8;
                int gn = bcol + nr, gk = k0 + c8;
                cp_async16(Bs + p * BSZ + nr * LDB + c8,
                           B + (size_t)gn * K + gk, (gn < N) && (gk < K));
            }
        }
        cp_commit();
    };

    // prologue: fill 2 pipeline stages
    load_tile(0, 0);
    if (nkt > 1) load_tile(1, 1);

    for (int kt = 0; kt < nkt; ++kt) {
        const int p = kt % NSTG;
        if (kt + 1 < nkt) cp_wait<1>(); else cp_wait<0>();
        __syncthreads();   // loads of buf p visible; all prior compute done

        __nv_bfloat16* as = As + p * ASZ + (wm * FM * 16) * LDA;
#pragma unroll
        for (int ks = 0; ks < 4; ks++) {
            wmma::fragment<wmma::matrix_a, 16, 16, 16, __nv_bfloat16,
                           wmma::row_major> af[FM];
#pragma unroll
            for (int i = 0; i < FM; i++)
                wmma::load_matrix_sync(af[i], as + (i * 16) * LDA + ks * 16, LDA);

            if (!BT) {
                wmma::fragment<wmma::matrix_b, 16, 16, 16, __nv_bfloat16,
                               wmma::row_major> bf[2];
                __nv_bfloat16* bs = Bs + p * BSZ + (ks * 16) * LDB + wn * 32;
#pragma unroll
                for (int j = 0; j < 2; j++)
                    wmma::load_matrix_sync(bf[j], bs + j * 16, LDB);
#pragma unroll
                for (int i = 0; i < FM; i++)
#pragma unroll
                    for (int j = 0; j < 2; j++)
                        wmma::mma_sync(acc[i][j], af[i], bf[j], acc[i][j]);
            } else {
                wmma::fragment<wmma::matrix_b, 16, 16, 16, __nv_bfloat16,
                               wmma::col_major> bf[2];
                __nv_bfloat16* bs = Bs + p * BSZ + (wn * 32) * LDB + ks * 16;
#pragma unroll
                for (int j = 0; j < 2; j++)
                    wmma::load_matrix_sync(bf[j], bs + (j * 16) * LDB, LDB);
#pragma unroll
                for (int i = 0; i < FM; i++)
#pragma unroll
                    for (int j = 0; j < 2; j++)
                        wmma::mma_sync(acc[i][j], af[i], bf[j], acc[i][j]);
            }
        }

        if (kt + 2 < nkt) load_tile(kt + 2, (kt + 2) % NSTG);
    }

    // ---- epilogue ----
    __syncthreads();                              // smem free for staging
    float* patch = (float*)smem_raw + wid * (16 * 20);

#pragma unroll
    for (int i = 0; i < FM; i++) {
#pragma unroll
        for (int j = 0; j < 2; j++) {
#pragma unroll
            for (int t = 0; t < acc[i][j].num_elements; t++) {
                float x = acc[i][j].x[t];
                if (EPI == EPI_TANH) x = tanhf(x);
                else if (EPI == EPI_SIG) x = 1.f / (1.f + __expf(-x));
                acc[i][j].x[t] = x;
            }
            const int r0 = brow + wm * FM * 16 + i * 16;
            const int c0 = bcol + wn * 32 + j * 16;
            if (r0 >= M || c0 >= N) continue;

            if (!OUTBF) {
                float* Cf = (float*)ga.C[g];
                if (r0 + 16 <= M && c0 + 16 <= N) {
                    wmma::store_matrix_sync(Cf + (size_t)r0 * N + c0, acc[i][j],
                                            N, wmma::mem_row_major);
                } else {
                    wmma::store_matrix_sync(patch, acc[i][j], 20,
                                            wmma::mem_row_major);
                    __syncwarp();
#pragma unroll
                    for (int t = 0; t < 8; t++) {
                        int e = lane + t * 32;
                        int rr = e >> 4, cc = e & 15;
                        if (r0 + rr < M && c0 + cc < N)
                            Cf[(size_t)(r0 + rr) * N + (c0 + cc)] =
                                patch[rr * 20 + cc];
                    }
                    __syncwarp();
                }
            } else {
                __nv_bfloat16* Cb = (__nv_bfloat16*)ga.C[g];
                wmma::store_matrix_sync(patch, acc[i][j], 20, wmma::mem_row_major);
                __syncwarp();
#pragma unroll
                for (int t = 0; t < 8; t++) {
                    int e = lane + t * 32;
                    int rr = e >> 4, cc = e & 15;
                    if (r0 + rr < M && c0 + cc < N)
                        Cb[(size_t)(r0 + rr) * N + (c0 + cc)] =
                            __float2bfloat16(patch[rr * 20 + cc]);
                }
                __syncwarp();
            }
        }
    }
}

// ---------------- host side ----------------
template <int EPI, bool BT, int BM, bool OUTBF>
static void launch(const GArgs& ga) {
    constexpr int LDA = 72, LDB = BT ? 72 : 136;
    constexpr int ASZ = BM * LDA;
    constexpr int BSZ = BT ? 128 * LDB : 64 * LDB;
    constexpr int SMB = 3 * (ASZ + BSZ) * 2;   // bytes (3 pipeline stages)
    cudaFuncSetAttribute(mm_bf16<EPI, BT, BM, OUTBF>,
                         cudaFuncAttributeMaxDynamicSharedMemorySize, SMB);
    dim3 grid((ga.N + 127) / 128, (ga.M + BM - 1) / BM, 4);
    mm_bf16<EPI, BT, BM, OUTBF><<<grid, 256, SMB>>>(ga);
}

extern "C" void kernel_launch(void* const* d_in, const int* in_sizes, int n_in,
                              void* d_out, int out_size)
{
    const float* omics[2] = {(const float*)d_in[0], (const float*)d_in[1]};
    const float* adj[4]   = {(const float*)d_in[2], (const float*)d_in[3],
                             (const float*)d_in[4], (const float*)d_in[5]};
    const float* W[4][3];
    for (int e = 0; e < 4; e++)
        for (int l = 0; l < 3; l++)
            W[e][l] = (const float*)d_in[6 + e * 3 + l];

    float* out = (float*)d_out;

    __nv_bfloat16 *adjB, *xB, *wB, *bA, *bB;
    cudaGetSymbolAddress((void**)&adjB, g_adj_bf);
    cudaGetSymbolAddress((void**)&xB, g_x_bf);
    cudaGetSymbolAddress((void**)&wB, g_w_bf);
    cudaGetSymbolAddress((void**)&bA, g_bufA);
    cudaGetSymbolAddress((void**)&bB, g_bufB);

    __nv_bfloat16* adj_bf[4];
    __nv_bfloat16* x_bf[2];
    __nv_bfloat16* w_bf[4][3];
    __nv_bfloat16 *bufA[4], *bufB[4];
    for (int e = 0; e < 4; e++) {
        adj_bf[e] = adjB + (size_t)e * NS * NS;
        for (int l = 0; l < 3; l++)
            w_bf[e][l] = wB + ((size_t)e * 3 + l) * NS * ENC1;
        bufA[e] = bA + (size_t)e * NS * ENC1;
        bufB[e] = bB + (size_t)e * NS * ENC1;
    }
    x_bf[0] = xB; x_bf[1] = xB + (size_t)NS * NS;

    // --- conversions: exactly 2 launches (ncu -s 5 then lands on a GEMM) ---
    {
        C6 c6;
        for (int e = 0; e < 4; e++) { c6.s[e] = adj[e]; c6.d[e] = adj_bf[e]; }
        c6.s[4] = omics[0]; c6.d[4] = x_bf[0];
        c6.s[5] = omics[1]; c6.d[5] = x_bf[1];
        c6.n = NS * NS;
        f2bf6_kernel<<<dim3(512, 6), 256>>>(c6);

        CW cw;
        const int wsz[3] = {NS * 256, 256 * 128, 128 * 64};
        for (int e = 0; e < 4; e++)
            for (int l = 0; l < 3; l++) {
                cw.s[e * 3 + l] = W[e][l];
                cw.d[e * 3 + l] = w_bf[e][l];
                cw.n[e * 3 + l] = wsz[l];
            }
        f2bfw_kernel<<<dim3(128, 12), 256>>>(cw);
    }

    GArgs ga;

    // S1: h1 = tanh(x @ W1)   [3000,256]  BM=96: 256 CTAs
    for (int e = 0; e < 4; e++) { ga.A[e] = x_bf[e & 1]; ga.B[e] = w_bf[e][0]; ga.C[e] = bufA[e]; }
    ga.M = NS; ga.N = 256; ga.K = NS;
    launch<EPI_TANH, false, 96, true>(ga);

    // S2: z1 = adj @ h1        [3000,256]
    for (int e = 0; e < 4; e++) { ga.A[e] = adj_bf[e]; ga.B[e] = bufA[e]; ga.C[e] = bufB[e]; }
    ga.M = NS; ga.N = 256; ga.K = NS;
    launch<EPI_NONE, false, 96, true>(ga);

    // S3: h2 = tanh(z1 @ W2)   [3000,128]  BM=32: 376 CTAs
    for (int e = 0; e < 4; e++) { ga.A[e] = bufB[e]; ga.B[e] = w_bf[e][1]; ga.C[e] = bufA[e]; }
    ga.M = NS; ga.N = 128; ga.K = 256;
    launch<EPI_TANH, false, 32, true>(ga);

    // S4: z2 = adj @ h2        [3000,128]   <-- ncu -s 5 capture target
    for (int e = 0; e < 4; e++) { ga.A[e] = adj_bf[e]; ga.B[e] = bufA[e]; ga.C[e] = bufB[e]; }
    ga.M = NS; ga.N = 128; ga.K = NS;
    launch<EPI_NONE, false, 32, true>(ga);

    // S5: h3 = z2 @ W3         [3000,64]
    for (int e = 0; e < 4; e++) { ga.A[e] = bufB[e]; ga.B[e] = w_bf[e][2]; ga.C[e] = bufA[e]; }
    ga.M = NS; ga.N = 64; ga.K = 128;
    launch<EPI_NONE, false, 32, true>(ga);

    // S6: z3 = adj @ h3        [3000,64]
    for (int e = 0; e < 4; e++) { ga.A[e] = adj_bf[e]; ga.B[e] = bufA[e]; ga.C[e] = bufB[e]; }
    ga.M = NS; ga.N = 64; ga.K = NS;
    launch<EPI_NONE, false, 32, true>(ga);

    // S7: out[e] = sigmoid(z3 @ z3^T)  [3000,3000] fp32
    for (int e = 0; e < 4; e++) {
        ga.A[e] = bufB[e]; ga.B[e] = bufB[e];
        ga.C[e] = out + (size_t)e * NS * NS;
    }
    ga.M = NS; ga.N = NS; ga.K = 64;
    launch<EPI_SIG, true, 128, false>(ga);
}